// round 1
// baseline (speedup 1.0000x reference)
#include <cuda_runtime.h>
#include <cstdint>

// Inverse 2D Haar DWT (even sizes):
//   a = (ll+lh+hl+hh)*0.5 -> x[2i,   2j]
//   b = (ll+lh-hl-hh)*0.5 -> x[2i,   2j+1]
//   c = (ll-lh+hl-hh)*0.5 -> x[2i+1, 2j]
//   d = (ll-lh-hl+hh)*0.5 -> x[2i+1, 2j+1]
//
// Shapes: inputs (4,64,256,256) fp32, output (4,64,512,512) fp32.
// Flat layout: plane = b*64+c (256 planes), each plane 256x256 in, 512x512 out.
//
// One thread processes a float4 (4 consecutive j) from each coefficient tensor
// and writes 4 float4s: two per output row (even row: a/b interleave, odd row:
// c/d interleave). Adjacent threads cover adjacent 32B chunks per row ->
// fully coalesced 128B sectors.

static constexpr int W4_IN  = 256 / 4;   // 64 float4 per input row
static constexpr int W4_OUT = 512 / 4;   // 128 float4 per output row
static constexpr int H_IN   = 256;
static constexpr int PLANE_OUT_F4 = 512 * 512 / 4;  // 65536 float4 per output plane

__global__ __launch_bounds__(256)
void haar_idwt2_kernel(const float4* __restrict__ ll,
                       const float4* __restrict__ lh,
                       const float4* __restrict__ hl,
                       const float4* __restrict__ hh,
                       float4* __restrict__ out,
                       int n_f4)  // total input float4 count = 4*64*256*256/4
{
    int q = blockIdx.x * blockDim.x + threadIdx.x;
    if (q >= n_f4) return;

    // q -> (plane, h, col4)
    int col4  = q & (W4_IN - 1);          // q % 64
    int r     = q >> 6;                   // combined plane*256 + h
    int h     = r & (H_IN - 1);           // r % 256
    int plane = r >> 8;                   // r / 256

    float4 vll = ll[q];
    float4 vlh = lh[q];
    float4 vhl = hl[q];
    float4 vhh = hh[q];

    // Polyphase components, scaled by 0.5
    float4 A, Bv, Cv, D;
    A.x  = (vll.x + vlh.x + vhl.x + vhh.x) * 0.5f;
    A.y  = (vll.y + vlh.y + vhl.y + vhh.y) * 0.5f;
    A.z  = (vll.z + vlh.z + vhl.z + vhh.z) * 0.5f;
    A.w  = (vll.w + vlh.w + vhl.w + vhh.w) * 0.5f;

    Bv.x = (vll.x + vlh.x - vhl.x - vhh.x) * 0.5f;
    Bv.y = (vll.y + vlh.y - vhl.y - vhh.y) * 0.5f;
    Bv.z = (vll.z + vlh.z - vhl.z - vhh.z) * 0.5f;
    Bv.w = (vll.w + vlh.w - vhl.w - vhh.w) * 0.5f;

    Cv.x = (vll.x - vlh.x + vhl.x - vhh.x) * 0.5f;
    Cv.y = (vll.y - vlh.y + vhl.y - vhh.y) * 0.5f;
    Cv.z = (vll.z - vlh.z + vhl.z - vhh.z) * 0.5f;
    Cv.w = (vll.w - vlh.w + vhl.w - vhh.w) * 0.5f;

    D.x  = (vll.x - vlh.x - vhl.x + vhh.x) * 0.5f;
    D.y  = (vll.y - vlh.y - vhl.y + vhh.y) * 0.5f;
    D.z  = (vll.z - vlh.z - vhl.z + vhh.z) * 0.5f;
    D.w  = (vll.w - vlh.w - vhl.w + vhh.w) * 0.5f;

    // Interleave into output rows
    // even row (2h):   [a0 b0 a1 b1] [a2 b2 a3 b3]
    // odd  row (2h+1): [c0 d0 c1 d1] [c2 d2 c3 d3]
    int base0 = plane * PLANE_OUT_F4 + (2 * h) * W4_OUT + 2 * col4;
    int base1 = base0 + W4_OUT;

    out[base0]     = make_float4(A.x,  Bv.x, A.y,  Bv.y);
    out[base0 + 1] = make_float4(A.z,  Bv.z, A.w,  Bv.w);
    out[base1]     = make_float4(Cv.x, D.x,  Cv.y, D.y);
    out[base1 + 1] = make_float4(Cv.z, D.z,  Cv.w, D.w);
}

extern "C" void kernel_launch(void* const* d_in, const int* in_sizes, int n_in,
                              void* d_out, int out_size)
{
    const float4* ll = (const float4*)d_in[0];
    const float4* lh = (const float4*)d_in[1];
    const float4* hl = (const float4*)d_in[2];
    const float4* hh = (const float4*)d_in[3];
    float4* out = (float4*)d_out;

    int n_f4 = in_sizes[0] / 4;           // 4*64*256*256/4 = 4,194,304
    int threads = 256;
    int blocks = (n_f4 + threads - 1) / threads;

    haar_idwt2_kernel<<<blocks, threads>>>(ll, lh, hl, hh, out, n_f4);
}

// round 2
// speedup vs baseline: 1.0558x; 1.0558x over previous
#include <cuda_runtime.h>
#include <cstdint>

// Inverse 2D Haar DWT, output-centric decomposition.
//
// Inputs: 4 x (4,64,256,256) fp32.  Output: (4,64,512,512) fp32.
//
// One thread handles one float2 (2 consecutive cols j, j+1) from each band
// and writes two float4s:
//   even output row 2h : {a_j, b_j, a_{j+1}, b_{j+1}}
//   odd  output row 2h+1: {c_j, d_j, c_{j+1}, d_{j+1}}
//
// Warp-wide, loads are 32 x 8B contiguous (2 full 128B sectors / LDG.64) and
// stores are 32 x 16B contiguous (4 full sectors / STG.128) -> zero
// partial-sector wavefronts. Streaming hints (.cs) since there is zero reuse.

static constexpr int W2_IN  = 256 / 2;        // 128 float2 per input row
static constexpr int H_IN   = 256;
static constexpr int W4_OUT = 512 / 4;        // 128 float4 per output row
static constexpr int PLANE_OUT_F4 = 512 * 512 / 4;  // 65536

__global__ __launch_bounds__(256)
void haar_idwt2_kernel(const float2* __restrict__ ll,
                       const float2* __restrict__ lh,
                       const float2* __restrict__ hl,
                       const float2* __restrict__ hh,
                       float4* __restrict__ out,
                       int n_f2)  // total float2 count = 4*64*256*128
{
    int f = blockIdx.x * blockDim.x + threadIdx.x;
    if (f >= n_f2) return;

    // f -> (plane, h, col2)
    int col2  = f & (W2_IN - 1);     // f % 128
    int r     = f >> 7;
    int h     = r & (H_IN - 1);      // r % 256
    int plane = r >> 8;

    float2 vll = __ldcs(&ll[f]);
    float2 vlh = __ldcs(&lh[f]);
    float2 vhl = __ldcs(&hl[f]);
    float2 vhh = __ldcs(&hh[f]);

    float a0 = (vll.x + vlh.x + vhl.x + vhh.x) * 0.5f;
    float b0 = (vll.x + vlh.x - vhl.x - vhh.x) * 0.5f;
    float c0 = (vll.x - vlh.x + vhl.x - vhh.x) * 0.5f;
    float d0 = (vll.x - vlh.x - vhl.x + vhh.x) * 0.5f;

    float a1 = (vll.y + vlh.y + vhl.y + vhh.y) * 0.5f;
    float b1 = (vll.y + vlh.y - vhl.y - vhh.y) * 0.5f;
    float c1 = (vll.y - vlh.y + vhl.y - vhh.y) * 0.5f;
    float d1 = (vll.y - vlh.y - vhl.y + vhh.y) * 0.5f;

    int idx0 = plane * PLANE_OUT_F4 + (2 * h) * W4_OUT + col2;  // even row
    int idx1 = idx0 + W4_OUT;                                   // odd row

    __stcs(&out[idx0], make_float4(a0, b0, a1, b1));
    __stcs(&out[idx1], make_float4(c0, d0, c1, d1));
}

extern "C" void kernel_launch(void* const* d_in, const int* in_sizes, int n_in,
                              void* d_out, int out_size)
{
    const float2* ll = (const float2*)d_in[0];
    const float2* lh = (const float2*)d_in[1];
    const float2* hl = (const float2*)d_in[2];
    const float2* hh = (const float2*)d_in[3];
    float4* out = (float4*)d_out;

    int n_f2 = in_sizes[0] / 2;       // 8,388,608
    int threads = 256;
    int blocks = (n_f2 + threads - 1) / threads;

    haar_idwt2_kernel<<<blocks, threads>>>(ll, lh, hl, hh, out, n_f2);
}